// round 15
// baseline (speedup 1.0000x reference)
#include <cuda_runtime.h>
#include <math.h>
#include <stdint.h>

#define NB   4
#define CIN  256
#define CCH  96
#define HHI  128
#define WHI  128
#define HWHI (HHI*WHI)
#define HLO  64
#define WLO  64
#define HWLO (HLO*WLO)
#define NSPL 6

// ---------------- scratch ----------------
#define O_CHR     0
#define O_CHR2    (O_CHR   + NB*CCH*HWHI)
#define O_CLR     (O_CHR2  + NB*CCH*HWHI)
#define O_PLR     (O_CLR   + NB*CCH*HWLO)
#define O_MHH     (O_PLR   + NB*CCH*HWLO)
#define O_MLH     (O_MHH   + NB*9*HWHI)
#define O_MLL     (O_MLH   + NB*25*HWHI)
#define O_MHL     (O_MLL   + NB*25*HWLO)
#define O_MASKHR  (O_MHL   + NB*9*HWLO)
#define O_PART_HI (O_MASKHR + NB*9*HWHI)
#define O_PART_LO (O_PART_HI + NSPL*NB*25*HWHI)
#define SCRATCH_TOTAL (O_PART_LO + NSPL*NB*25*HWLO)

__device__ float g_scratch[SCRATCH_TOTAL];

template<int K>
__device__ __forceinline__ void wsoftmax(float* v, const float* hs) {
    float mx = v[0];
#pragma unroll
    for (int i = 1; i < K; i++) mx = fmaxf(mx, v[i]);
    float s = 0.f;
#pragma unroll
    for (int i = 0; i < K; i++) { v[i] = __expf(v[i] - mx) * hs[i]; s += v[i]; }
    float inv = 1.f / s;
#pragma unroll
    for (int i = 0; i < K; i++) v[i] *= inv;
}

template<int H, int W>
__device__ __forceinline__ float ldclamp(const float* __restrict__ base, int y, int x) {
    bool ok = ((unsigned)y < (unsigned)H) && ((unsigned)x < (unsigned)W);
    int ys = min(max(y, 0), H - 1);
    int xs = min(max(x, 0), W - 1);
    float v = base[(size_t)ys * W + xs];
    return ok ? v : 0.f;
}

__device__ __forceinline__ uint32_t smem_u32(const void* p) {
    uint32_t a;
    asm("{ .reg .u64 t; cvta.to.shared.u64 t, %1; cvt.u32.u64 %0, t; }" : "=r"(a) : "l"(p));
    return a;
}
__device__ __forceinline__ void cp16(uint32_t dst, const void* src) {
    asm volatile("cp.async.cg.shared.global [%0], [%1], 16;" :: "r"(dst), "l"(src));
}
__device__ __forceinline__ void cp4z(uint32_t dst, const void* src, int szbytes) {
    asm volatile("cp.async.ca.shared.global [%0], [%1], 4, %2;" :: "r"(dst), "l"(src), "r"(szbytes));
}

// Precomputed halo-staging geometry (sync LDG version)
template<int H, int W, int TH, int TW, int NTHREADS>
struct StageGeom {
    static constexpr int HALO_C = TW + 2;
    static constexpr int HALO   = (TH + 2) * HALO_C;
    static constexpr int TWP    = TW + 4;
    static constexpr int NLD    = (HALO + NTHREADS - 1) / NTHREADS;
    int  offg[NLD];
    int  offd[NLD];
    bool ok[NLD];
    __device__ __forceinline__ void init(int t, int gy0, int gx0) {
#pragma unroll
        for (int j = 0; j < NLD; j++) {
            int e = j * NTHREADS + t;
            bool val = (e < HALO);
            int ec = val ? e : 0;
            int r = ec / HALO_C;
            int c = ec - r * HALO_C;
            int y = gy0 + r - 1, x = gx0 + c - 1;
            ok[j] = val && ((unsigned)y < (unsigned)H) && ((unsigned)x < (unsigned)W);
            int yc = min(max(y, 0), H - 1);
            int xc = min(max(x, 0), W - 1);
            offg[j] = yc * W + xc;
            offd[j] = val ? (r * TWP + c) : (TWP - 1);
        }
    }
    __device__ __forceinline__ void run(const float* __restrict__ xc, float* __restrict__ xd) const {
#pragma unroll
        for (int j = 0; j < NLD; j++) {
            float v = xc[offg[j]];
            xd[offd[j]] = ok[j] ? v : 0.f;
        }
    }
};

// async variant: cp.async 4B with zero-fill select (ok -> 4 bytes, else 0)
template<int H, int W, int TH, int TW, int NTHREADS>
struct StageGeomA {
    static constexpr int HALO_C = TW + 2;
    static constexpr int HALO   = (TH + 2) * HALO_C;
    static constexpr int TWP    = TW + 4;
    static constexpr int NLD    = (HALO + NTHREADS - 1) / NTHREADS;
    int offg[NLD];
    int offdB[NLD];   // smem byte offset within one channel plane
    int sz[NLD];      // 4 if in-bounds else 0 (zero-fill)
    __device__ __forceinline__ void init(int t, int gy0, int gx0) {
#pragma unroll
        for (int j = 0; j < NLD; j++) {
            int e = j * NTHREADS + t;
            bool val = (e < HALO);
            int ec = val ? e : 0;
            int r = ec / HALO_C;
            int c = ec - r * HALO_C;
            int y = gy0 + r - 1, x = gx0 + c - 1;
            bool ok = val && ((unsigned)y < (unsigned)H) && ((unsigned)x < (unsigned)W);
            int yc = min(max(y, 0), H - 1);
            int xc = min(max(x, 0), W - 1);
            offg[j]  = yc * W + xc;
            offdB[j] = (val ? (r * TWP + c) : (TWP - 1)) * 4;
            sz[j]    = ok ? 4 : 0;
        }
    }
    __device__ __forceinline__ void run_async(const float* __restrict__ xc, uint32_t xd) const {
#pragma unroll
        for (int j = 0; j < NLD; j++)
            cp4z(xd + (uint32_t)offdB[j], xc + offg[j], sz[j]);
    }
};

// ---------------- 1x1 conv = GEMM (scalar FFMA, cp.async double-buffered) ----------------
__global__ void __launch_bounds__(256)
gemm1x1_k(const float* __restrict__ X, const float* __restrict__ W,
          const float* __restrict__ bias, float* __restrict__ Y, int HW)
{
    __shared__ float Ws[2][16][32];
    __shared__ float Xs[2][16][128];
    int t   = threadIdx.x;
    int pxt = blockIdx.x, cot = blockIdx.y, nb = blockIdx.z;
    const float* Xb = X + (size_t)nb * CIN * HW + pxt * 128;
    const float* Wb = W + (size_t)cot * 32 * CIN;
    float acc[4][4];
#pragma unroll
    for (int i = 0; i < 4; i++)
#pragma unroll
        for (int j = 0; j < 4; j++) acc[i][j] = 0.f;

    int co_s = (t >> 5) * 4;
    int px_s = (t & 31) * 4;
    int xc = t >> 4;
    int xp = (t & 15) * 8;
    int wc = t >> 2;
    int wk = (t & 3) * 4;

    uint32_t xdst0 = smem_u32(&Xs[0][xc][xp]);
    uint32_t xdst1 = smem_u32(&Xs[1][xc][xp]);

    {
        const float* src = Xb + (size_t)xc * HW + xp;
        cp16(xdst0, src);
        cp16(xdst0 + 16, src + 4);
        asm volatile("cp.async.commit_group;");
        if (t < 128) {
            float4 w4 = *(const float4*)(Wb + (size_t)wc * CIN + wk);
            Ws[0][wk + 0][wc] = w4.x; Ws[0][wk + 1][wc] = w4.y;
            Ws[0][wk + 2][wc] = w4.z; Ws[0][wk + 3][wc] = w4.w;
        }
    }

    for (int c = 0; c < 16; c++) {
        int buf = c & 1;
        asm volatile("cp.async.wait_group 0;");
        __syncthreads();
        if (c < 15) {
            int kc = (c + 1) * 16;
            const float* src = Xb + (size_t)(kc + xc) * HW + xp;
            uint32_t xd = (buf ? xdst0 : xdst1);
            cp16(xd, src);
            cp16(xd + 16, src + 4);
            asm volatile("cp.async.commit_group;");
            if (t < 128) {
                float4 w4 = *(const float4*)(Wb + (size_t)wc * CIN + kc + wk);
                float (*Wn)[32] = Ws[buf ^ 1];
                Wn[wk + 0][wc] = w4.x; Wn[wk + 1][wc] = w4.y;
                Wn[wk + 2][wc] = w4.z; Wn[wk + 3][wc] = w4.w;
            }
        }
#pragma unroll
        for (int k = 0; k < 16; k++) {
            float4 a = *(const float4*)&Ws[buf][k][co_s];
            float4 b = *(const float4*)&Xs[buf][k][px_s];
            acc[0][0] = fmaf(a.x, b.x, acc[0][0]); acc[0][1] = fmaf(a.x, b.y, acc[0][1]);
            acc[0][2] = fmaf(a.x, b.z, acc[0][2]); acc[0][3] = fmaf(a.x, b.w, acc[0][3]);
            acc[1][0] = fmaf(a.y, b.x, acc[1][0]); acc[1][1] = fmaf(a.y, b.y, acc[1][1]);
            acc[1][2] = fmaf(a.y, b.z, acc[1][2]); acc[1][3] = fmaf(a.y, b.w, acc[1][3]);
            acc[2][0] = fmaf(a.z, b.x, acc[2][0]); acc[2][1] = fmaf(a.z, b.y, acc[2][1]);
            acc[2][2] = fmaf(a.z, b.z, acc[2][2]); acc[2][3] = fmaf(a.z, b.w, acc[2][3]);
            acc[3][0] = fmaf(a.w, b.x, acc[3][0]); acc[3][1] = fmaf(a.w, b.y, acc[3][1]);
            acc[3][2] = fmaf(a.w, b.z, acc[3][2]); acc[3][3] = fmaf(a.w, b.w, acc[3][3]);
        }
    }
    float* Yb = Y + (size_t)nb * CCH * HW + (size_t)(cot * 32) * HW + pxt * 128;
#pragma unroll
    for (int i = 0; i < 4; i++) {
        float bv = bias ? __ldg(&bias[cot * 32 + co_s + i]) : 0.f;
        float4 o = make_float4(acc[i][0] + bv, acc[i][1] + bv, acc[i][2] + bv, acc[i][3] + bv);
        *(float4*)(Yb + (size_t)(co_s + i) * HW + px_s) = o;
    }
}

// ---------------- 3x3 conv split-K partial, 2 px/thread (CO=25) ----------------
template<int CO, int TH, int TW, int CSPL, int H, int Wd>
__global__ void __launch_bounds__(128)
conv3x3_part_k(const float* __restrict__ X, const float* __restrict__ W,
               float* __restrict__ P)
{
    constexpr int CH = 8;
    constexpr int HW = H * Wd;
    __shared__ float xs[CH][TH + 2][TW + 4];
    __shared__ float ws[CH][CO][12];
    int t    = threadIdx.x;
    int row  = t / (TW / 2);
    int col2 = (t % (TW / 2)) * 2;
    int gx0 = blockIdx.x * TW;
    int gy0 = blockIdx.y * TH;
    int nb = blockIdx.z / NSPL;
    int sp = blockIdx.z % NSPL;
    int c0 = sp * CSPL;
    const float* Xb = X + (size_t)nb * CCH * HW;

    StageGeom<H, Wd, TH, TW, 128> sg;
    sg.init(t, gy0, gx0);

    float acc[CO][2];
#pragma unroll
    for (int i = 0; i < CO; i++) { acc[i][0] = 0.f; acc[i][1] = 0.f; }

    for (int cc = c0; cc < c0 + CSPL; cc += CH) {
#pragma unroll
        for (int ch = 0; ch < CH; ch++)
            sg.run(Xb + (size_t)(cc + ch) * HW, &xs[ch][0][0]);
        for (int p = t; p < CH * CO; p += 128) {
            int ch = p / CO, co = p - ch * CO;
            const float* wsrc = W + (size_t)co * CCH * 9 + (size_t)(cc + ch) * 9;
            float* wdst = &ws[ch][co][0];
#pragma unroll
            for (int k = 0; k < 9; k++) wdst[k] = wsrc[k];
        }
        __syncthreads();
#pragma unroll 2
        for (int ch = 0; ch < CH; ch++) {
            float xv[3][4];
#pragma unroll
            for (int r = 0; r < 3; r++) {
                float2 a0 = *(const float2*)&xs[ch][row + r][col2];
                float2 a1 = *(const float2*)&xs[ch][row + r][col2 + 2];
                xv[r][0] = a0.x; xv[r][1] = a0.y; xv[r][2] = a1.x; xv[r][3] = a1.y;
            }
#pragma unroll
            for (int co = 0; co < CO; co++) {
                float4 wa = *(const float4*)&ws[ch][co][0];
                float4 wb = *(const float4*)&ws[ch][co][4];
                float  w8 = ws[ch][co][8];
                float s0, s1;
                s0 = wa.x * xv[0][0];            s1 = wa.x * xv[0][1];
                s0 = fmaf(wa.y, xv[0][1], s0);   s1 = fmaf(wa.y, xv[0][2], s1);
                s0 = fmaf(wa.z, xv[0][2], s0);   s1 = fmaf(wa.z, xv[0][3], s1);
                s0 = fmaf(wa.w, xv[1][0], s0);   s1 = fmaf(wa.w, xv[1][1], s1);
                s0 = fmaf(wb.x, xv[1][1], s0);   s1 = fmaf(wb.x, xv[1][2], s1);
                s0 = fmaf(wb.y, xv[1][2], s0);   s1 = fmaf(wb.y, xv[1][3], s1);
                s0 = fmaf(wb.z, xv[2][0], s0);   s1 = fmaf(wb.z, xv[2][1], s1);
                s0 = fmaf(wb.w, xv[2][1], s0);   s1 = fmaf(wb.w, xv[2][2], s1);
                s0 = fmaf(w8 ,  xv[2][2], s0);   s1 = fmaf(w8 ,  xv[2][3], s1);
                acc[co][0] += s0; acc[co][1] += s1;
            }
        }
        __syncthreads();
    }
    float* Pb = P + ((size_t)sp * NB + nb) * CO * HW + (gy0 + row) * Wd + gx0 + col2;
#pragma unroll
    for (int co = 0; co < CO; co++)
        *(float2*)&Pb[(size_t)co * HW] = make_float2(acc[co][0], acc[co][1]);
}

// ---------------- 3x3 conv split-K partial, 4 px/thread (CO=9) ----------------
template<int CO, int TH, int TW, int CSPL, int H, int Wd>
__global__ void __launch_bounds__(128)
conv3x3_part4_k(const float* __restrict__ X, const float* __restrict__ W,
                float* __restrict__ P)
{
    constexpr int CH = 8;
    constexpr int HW = H * Wd;
    __shared__ float xs[CH][TH + 2][TW + 4];
    __shared__ float ws[CH][CO][12];
    int t    = threadIdx.x;
    int row  = t / (TW / 4);
    int col4 = (t % (TW / 4)) * 4;
    int gx0 = blockIdx.x * TW;
    int gy0 = blockIdx.y * TH;
    int nb = blockIdx.z / NSPL;
    int sp = blockIdx.z % NSPL;
    int c0 = sp * CSPL;
    const float* Xb = X + (size_t)nb * CCH * HW;

    StageGeom<H, Wd, TH, TW, 128> sg;
    sg.init(t, gy0, gx0);

    float acc[CO][4];
#pragma unroll
    for (int i = 0; i < CO; i++)
#pragma unroll
        for (int j = 0; j < 4; j++) acc[i][j] = 0.f;

    for (int cc = c0; cc < c0 + CSPL; cc += CH) {
#pragma unroll
        for (int ch = 0; ch < CH; ch++)
            sg.run(Xb + (size_t)(cc + ch) * HW, &xs[ch][0][0]);
        for (int p = t; p < CH * CO; p += 128) {
            int ch = p / CO, co = p - ch * CO;
            const float* wsrc = W + (size_t)co * CCH * 9 + (size_t)(cc + ch) * 9;
            float* wdst = &ws[ch][co][0];
#pragma unroll
            for (int k = 0; k < 9; k++) wdst[k] = wsrc[k];
        }
        __syncthreads();
#pragma unroll 2
        for (int ch = 0; ch < CH; ch++) {
            float xv[3][6];
#pragma unroll
            for (int r = 0; r < 3; r++) {
                float2 a0 = *(const float2*)&xs[ch][row + r][col4];
                float2 a1 = *(const float2*)&xs[ch][row + r][col4 + 2];
                float2 a2 = *(const float2*)&xs[ch][row + r][col4 + 4];
                xv[r][0] = a0.x; xv[r][1] = a0.y; xv[r][2] = a1.x;
                xv[r][3] = a1.y; xv[r][4] = a2.x; xv[r][5] = a2.y;
            }
#pragma unroll
            for (int co = 0; co < CO; co++) {
                float4 wa = *(const float4*)&ws[ch][co][0];
                float4 wb = *(const float4*)&ws[ch][co][4];
                float  w8 = ws[ch][co][8];
#pragma unroll
                for (int j = 0; j < 4; j++) {
                    float s = acc[co][j];
                    s = fmaf(wa.x, xv[0][j    ], s);
                    s = fmaf(wa.y, xv[0][j + 1], s);
                    s = fmaf(wa.z, xv[0][j + 2], s);
                    s = fmaf(wa.w, xv[1][j    ], s);
                    s = fmaf(wb.x, xv[1][j + 1], s);
                    s = fmaf(wb.y, xv[1][j + 2], s);
                    s = fmaf(wb.z, xv[2][j    ], s);
                    s = fmaf(wb.w, xv[2][j + 1], s);
                    s = fmaf(w8 ,  xv[2][j + 2], s);
                    acc[co][j] = s;
                }
            }
        }
        __syncthreads();
    }
    float* Pb = P + ((size_t)sp * NB + nb) * CO * HW + (gy0 + row) * Wd + gx0 + col4;
#pragma unroll
    for (int co = 0; co < CO; co++)
        *(float4*)&Pb[(size_t)co * HW] = make_float4(acc[co][0], acc[co][1], acc[co][2], acc[co][3]);
}

// ---------------- reduce NSPL partials + bias ----------------
__global__ void __launch_bounds__(256)
reduceN_bias_k(const float* __restrict__ P, const float* __restrict__ bias,
               float* __restrict__ Y, int CO, int HW, int perSplit)
{
    int i = (blockIdx.x * blockDim.x + threadIdx.x) * 4;
    if (i >= perSplit) return;
    float4 s = *(const float4*)&P[i];
#pragma unroll
    for (int k = 1; k < NSPL; k++) {
        float4 a = *(const float4*)&P[(size_t)k * perSplit + i];
        s.x += a.x; s.y += a.y; s.z += a.z; s.w += a.w;
    }
    int co = (i / HW) % CO;
    float bv = __ldg(&bias[co]);
    s.x += bv; s.y += bv; s.z += bv; s.w += bv;
    *(float4*)&Y[i] = s;
}

// ---------------- residual CARAFE k=3 up=1, cp.async double-buffered ----------------
template<bool NORM, int CCHUNK>
__global__ void __launch_bounds__(128)
carafe3_k(const float* __restrict__ X, const float* __restrict__ M,
          const float* __restrict__ ham, float* __restrict__ Y, int C, int nCT)
{
    constexpr int CH = 8;
    constexpr int NCHK = CCHUNK / CH;
    constexpr int PLANE_B = 6 * 68 * 4;
    __shared__ float xs[2][CH][6][68];
    int t = threadIdx.x;
    int row  = t >> 5;
    int col2 = (t & 31) * 2;
    int gx0 = blockIdx.x * 64;
    int gy0 = blockIdx.y * 4;
    int nb = blockIdx.z / nCT;
    int c0 = (blockIdx.z % nCT) * CCHUNK;
    int py = gy0 + row, px = gx0 + col2;

    StageGeomA<HHI, WHI, 4, 64, 128> sg;
    sg.init(t, gy0, gx0);
    uint32_t xb[2];
    xb[0] = smem_u32(&xs[0][0][0][0]);
    xb[1] = smem_u32(&xs[1][0][0][0]);

    float w0[9], w1[9];
    {
        const float* Mb = M + (size_t)nb * 9 * HWHI + py * WHI + px;
#pragma unroll
        for (int k = 0; k < 9; k++) { w0[k] = Mb[(size_t)k * HWHI]; w1[k] = Mb[(size_t)k * HWHI + 1]; }
    }
    if (NORM) {
        float hv[9];
#pragma unroll
        for (int k = 0; k < 9; k++) hv[k] = __ldg(&ham[k]);
        wsoftmax<9>(w0, hv);
        wsoftmax<9>(w1, hv);
    }
    const float* Xb = X + (size_t)nb * C * HWHI;
    float*       Yb = Y + (size_t)nb * C * HWHI + (size_t)py * WHI + px;

    // prologue: stage chunk 0 into buf 0
#pragma unroll
    for (int ch = 0; ch < CH; ch++)
        sg.run_async(Xb + (size_t)(c0 + ch) * HWHI, xb[0] + ch * PLANE_B);
    asm volatile("cp.async.commit_group;");

    for (int ci = 0; ci < NCHK; ci++) {
        int buf = ci & 1;
        asm volatile("cp.async.wait_group 0;");
        __syncthreads();
        if (ci + 1 < NCHK) {
            int cc2 = c0 + (ci + 1) * CH;
            uint32_t xd = xb[buf ^ 1];
#pragma unroll
            for (int ch = 0; ch < CH; ch++)
                sg.run_async(Xb + (size_t)(cc2 + ch) * HWHI, xd + ch * PLANE_B);
            asm volatile("cp.async.commit_group;");
        }
        int cc = c0 + ci * CH;
#pragma unroll
        for (int ch = 0; ch < CH; ch++) {
            float xv[3][4];
#pragma unroll
            for (int r = 0; r < 3; r++) {
                float2 a0 = *(const float2*)&xs[buf][ch][row + r][col2];
                float2 a1 = *(const float2*)&xs[buf][ch][row + r][col2 + 2];
                xv[r][0] = a0.x; xv[r][1] = a0.y; xv[r][2] = a1.x; xv[r][3] = a1.y;
            }
            float s0 = 0.f, s1 = 0.f;
#pragma unroll
            for (int p = 0; p < 3; p++)
#pragma unroll
                for (int q = 0; q < 3; q++) {
                    s0 = fmaf(w0[p * 3 + q], xv[p][q],     s0);
                    s1 = fmaf(w1[p * 3 + q], xv[p][q + 1], s1);
                }
            float2 o = make_float2(2.f * xv[1][1] - s0, 2.f * xv[1][2] - s1);
            *(float2*)&Yb[(size_t)(cc + ch) * HWHI] = o;
        }
        // next iteration's top barrier orders buffer reuse
    }
}

// ---------------- mask_lr_n ----------------
__global__ void __launch_bounds__(256)
mask_fuse_lr_k(const float* __restrict__ mlh, const float* __restrict__ mll,
               const float* __restrict__ ham5, float* __restrict__ out)
{
    __shared__ float xs[25][12][12];
    __shared__ float hs[25];
    int t = threadIdx.x;
    int tx = t & 15, ty = t >> 4;
    int gx0 = blockIdx.x * 16, gy0 = blockIdx.y * 16, nb = blockIdx.z;
    int ly0 = gy0 / 2 - 2, lx0 = gx0 / 2 - 2;
    if (t < 25) hs[t] = ham5[t];
    if (ty < 12 && tx < 12) {
        int gy = ly0 + ty, gx = lx0 + tx;
#pragma unroll
        for (int ch = 0; ch < 25; ch++)
            xs[ch][ty][tx] = ldclamp<HLO, WLO>(mll + ((size_t)nb * 25 + ch) * HWLO, gy, gx);
    }
    __syncthreads();
    int py = gy0 + ty, px = gx0 + tx;
    float m[25];
    {
        const float* p = mlh + (size_t)nb * 25 * HWHI + py * WHI + px;
#pragma unroll
        for (int ch = 0; ch < 25; ch++) m[ch] = p[(size_t)ch * HWHI];
    }
    float wgt[25];
#pragma unroll
    for (int ch = 0; ch < 25; ch++) wgt[ch] = m[ch];
    wsoftmax<25>(wgt, hs);

    int rl = ty >> 1, cl = tx >> 1;
    float o[25];
#pragma unroll
    for (int ch = 0; ch < 25; ch++) {
        float s = 0.f;
#pragma unroll
        for (int p = 0; p < 5; p++)
#pragma unroll
            for (int q = 0; q < 5; q++)
                s = fmaf(wgt[p * 5 + q], xs[ch][rl + p][cl + q], s);
        o[ch] = m[ch] + s;
    }
    wsoftmax<25>(o, hs);
    float* op = out + (size_t)nb * 25 * HWHI + py * WHI + px;
#pragma unroll
    for (int ch = 0; ch < 25; ch++) op[(size_t)ch * HWHI] = o[ch];
}

// ---------------- mask_hr_n ----------------
__global__ void __launch_bounds__(256)
mask_fuse_hr_k(const float* __restrict__ mhh, const float* __restrict__ mhl,
               const float* __restrict__ maskn, const float* __restrict__ ham3,
               float* __restrict__ outm)
{
    __shared__ float xs[9][12][12];
    __shared__ float hs[9];
    int t = threadIdx.x;
    int tx = t & 15, ty = t >> 4;
    int gx0 = blockIdx.x * 16, gy0 = blockIdx.y * 16, nb = blockIdx.z;
    int ly0 = gy0 / 2 - 2, lx0 = gx0 / 2 - 2;
    if (t < 9) hs[t] = ham3[t];
    if (ty < 12 && tx < 12) {
        int gy = ly0 + ty, gx = lx0 + tx;
#pragma unroll
        for (int ch = 0; ch < 9; ch++)
            xs[ch][ty][tx] = ldclamp<HLO, WLO>(mhl + ((size_t)nb * 9 + ch) * HWLO, gy, gx);
    }
    __syncthreads();
    int py = gy0 + ty, px = gx0 + tx;
    float wgt[25];
    {
        const float* p = maskn + (size_t)nb * 25 * HWHI + py * WHI + px;
#pragma unroll
        for (int ch = 0; ch < 25; ch++) wgt[ch] = p[(size_t)ch * HWHI];
    }
    int rl = ty >> 1, cl = tx >> 1;
    float o[9];
    const float* mb = mhh + (size_t)nb * 9 * HWHI + py * WHI + px;
#pragma unroll
    for (int ch = 0; ch < 9; ch++) {
        float s = 0.f;
#pragma unroll
        for (int p = 0; p < 5; p++)
#pragma unroll
            for (int q = 0; q < 5; q++)
                s = fmaf(wgt[p * 5 + q], xs[ch][rl + p][cl + q], s);
        o[ch] = mb[(size_t)ch * HWHI] + s;
    }
    wsoftmax<9>(o, hs);
    float* op = outm + (size_t)nb * 9 * HWHI + py * WHI + px;
#pragma unroll
    for (int ch = 0; ch < 9; ch++) op[(size_t)ch * HWHI] = o[ch];
}

// ---------------- lr_out = carafe(P, mask_lr_n, 5, up2) + b_proj ----------------
__global__ void __launch_bounds__(256)
carafe_proj_k(const float* __restrict__ P, const float* __restrict__ maskn,
              const float* __restrict__ bproj, float* __restrict__ out)
{
    __shared__ float xs[8][12][12];
    int t = threadIdx.x;
    int tx = t & 15, ty = t >> 4;
    int gx0 = blockIdx.x * 16, gy0 = blockIdx.y * 16;
    int nb = blockIdx.z >> 2;
    int c0 = (blockIdx.z & 3) * 24;
    int ly0 = gy0 / 2 - 2, lx0 = gx0 / 2 - 2;
    int py = gy0 + ty, px = gx0 + tx;
    int rl = ty >> 1, cl = tx >> 1;

    float wgt[25];
    {
        const float* p = maskn + (size_t)nb * 25 * HWHI + py * WHI + px;
#pragma unroll
        for (int ch = 0; ch < 25; ch++) wgt[ch] = p[(size_t)ch * HWHI];
    }
    const float* Pb = P + (size_t)nb * CCH * HWLO;
    bool ld_ok = (ty < 12 && tx < 12);
    int gy = ly0 + ty, gx = lx0 + tx;

    for (int cc = c0; cc < c0 + 24; cc += 8) {
        if (ld_ok) {
#pragma unroll
            for (int ch = 0; ch < 8; ch++)
                xs[ch][ty][tx] = ldclamp<HLO, WLO>(Pb + (size_t)(cc + ch) * HWLO, gy, gx);
        }
        __syncthreads();
#pragma unroll
        for (int ch = 0; ch < 8; ch++) {
            float s = 0.f;
#pragma unroll
            for (int p = 0; p < 5; p++)
#pragma unroll
                for (int q = 0; q < 5; q++)
                    s = fmaf(wgt[p * 5 + q], xs[ch][rl + p][cl + q], s);
            out[((size_t)nb * CCH + cc + ch) * HWHI + py * WHI + px] = s + __ldg(&bproj[cc + ch]);
        }
        __syncthreads();
    }
}

// ---------------- launch ----------------
static cudaStream_t g_s1 = nullptr;
static cudaEvent_t  g_evA = nullptr, g_evB = nullptr, g_evC = nullptr, g_evD = nullptr;

extern "C" void kernel_launch(void* const* d_in, const int* in_sizes, int n_in,
                              void* d_out, int out_size)
{
    if (!g_s1) {
        cudaStreamCreateWithFlags(&g_s1, cudaStreamNonBlocking);
        cudaEventCreateWithFlags(&g_evA, cudaEventDisableTiming);
        cudaEventCreateWithFlags(&g_evB, cudaEventDisableTiming);
        cudaEventCreateWithFlags(&g_evC, cudaEventDisableTiming);
        cudaEventCreateWithFlags(&g_evD, cudaEventDisableTiming);
    }
    const float* hr     = (const float*)d_in[0];
    const float* lr     = (const float*)d_in[1];
    const float* W_hrc  = (const float*)d_in[2];
    const float* b_hrc  = (const float*)d_in[3];
    const float* W_lrc  = (const float*)d_in[4];
    const float* b_lrc  = (const float*)d_in[5];
    const float* W_enc  = (const float*)d_in[6];
    const float* b_enc  = (const float*)d_in[7];
    const float* W_enc2 = (const float*)d_in[8];
    const float* b_enc2 = (const float*)d_in[9];
    const float* W_proj = (const float*)d_in[10];
    const float* b_proj = (const float*)d_in[11];
    const float* ham5   = (const float*)d_in[12];
    const float* ham3   = (const float*)d_in[13];
    float* out = (float*)d_out;

    float* base = nullptr;
    cudaGetSymbolAddress((void**)&base, g_scratch);
    float* chr     = base + O_CHR;
    float* chr2    = base + O_CHR2;
    float* clr     = base + O_CLR;
    float* plr     = base + O_PLR;
    float* mhh     = base + O_MHH;
    float* mlh     = base + O_MLH;
    float* mll     = base + O_MLL;
    float* mhl     = base + O_MHL;
    float* maskhr  = base + O_MASKHR;
    float* part_hi = base + O_PART_HI;
    float* part_lo = base + O_PART_LO;

    float* out_mask = out;
    float* out_hr   = out + (size_t)NB * 25 * HWHI;
    float* out_lr   = out_hr + (size_t)NB * CIN * HWHI;

    cudaStream_t s0 = 0;

    // fork
    cudaEventRecord(g_evA, s0);
    cudaStreamWaitEvent(g_s1, g_evA, 0);

    // (1..4) s0 head
    gemm1x1_k<<<dim3(HWHI / 128, 3, NB), 256, 0, s0>>>(hr, W_hrc, b_hrc, chr, HWHI);                       // 1
    conv3x3_part4_k<9, 8, 64, 16, HHI, WHI><<<dim3(2, 16, NB * NSPL), 128, 0, s0>>>(chr, W_enc2, part_hi); // 2
    reduceN_bias_k<<<(NB * 9 * HWHI / 4 + 255) / 256, 256, 0, s0>>>(part_hi, b_enc2, mhh, 9, HWHI, NB * 9 * HWHI); // 3
    carafe3_k<true, 32><<<dim3(2, 32, NB * 3), 128, 0, s0>>>(chr, mhh, ham3, chr2, CCH, 3);                // 4
    // (5) s1 first kernel
    gemm1x1_k<<<dim3(HWLO / 128, 3, NB), 256, 0, g_s1>>>(lr, W_lrc, b_lrc, clr, HWLO);                     // 5
    // (6) conv25-hi profiled by ncu -s 5 -c 1
    conv3x3_part_k<25, 4, 64, 16, HHI, WHI><<<dim3(2, 32, NB * NSPL), 128, 0, s0>>>(chr2, W_enc, part_hi); // 6
    reduceN_bias_k<<<(NB * 25 * HWHI / 4 + 255) / 256, 256, 0, s0>>>(part_hi, b_enc, mlh, 25, HWHI, NB * 25 * HWHI);

    // rest of s1 low-res chain
    gemm1x1_k<<<dim3(HWLO / 128, 3, NB), 256, 0, g_s1>>>(lr, W_proj, nullptr, plr, HWLO);
    conv3x3_part_k<25, 8, 32, 16, HLO, WLO><<<dim3(2, 8, NB * NSPL), 128, 0, g_s1>>>(clr, W_enc, part_lo);
    reduceN_bias_k<<<(NB * 25 * HWLO / 4 + 255) / 256, 256, 0, g_s1>>>(part_lo, b_enc, mll, 25, HWLO, NB * 25 * HWLO);
    conv3x3_part4_k<9, 16, 32, 16, HLO, WLO><<<dim3(2, 4, NB * NSPL), 128, 0, g_s1>>>(clr, W_enc2, part_lo);
    reduceN_bias_k<<<(NB * 9 * HWLO / 4 + 255) / 256, 256, 0, g_s1>>>(part_lo, b_enc2, mhl, 9, HWLO, NB * 9 * HWLO);
    cudaEventRecord(g_evB, g_s1);

    // join lr chain, compute mask_lr_n
    cudaStreamWaitEvent(s0, g_evB, 0);
    mask_fuse_lr_k<<<dim3(8, 8, NB), 256, 0, s0>>>(mlh, mll, ham5, out_mask);

    // fork: carafe_proj only needs out_mask + plr
    cudaEventRecord(g_evC, s0);
    cudaStreamWaitEvent(g_s1, g_evC, 0);
    carafe_proj_k<<<dim3(8, 8, NB * 4), 256, 0, g_s1>>>(plr, out_mask, b_proj, out_lr);
    cudaEventRecord(g_evD, g_s1);

    // s0: mask_hr_n + hr residual
    mask_fuse_hr_k<<<dim3(8, 8, NB), 256, 0, s0>>>(mhh, mhl, out_mask, ham3, maskhr);
    carafe3_k<false, 32><<<dim3(2, 32, NB * 8), 128, 0, s0>>>(hr, maskhr, ham3, out_hr, CIN, 8);

    // join
    cudaStreamWaitEvent(s0, g_evD, 0);
}

// round 16
// speedup vs baseline: 1.0881x; 1.0881x over previous
#include <cuda_runtime.h>
#include <math.h>
#include <stdint.h>

#define NB   4
#define CIN  256
#define CCH  96
#define HHI  128
#define WHI  128
#define HWHI (HHI*WHI)
#define HLO  64
#define WLO  64
#define HWLO (HLO*WLO)
#define NSPL 6

// ---------------- scratch ----------------
#define O_CHR     0
#define O_CHR2    (O_CHR   + NB*CCH*HWHI)
#define O_CLR     (O_CHR2  + NB*CCH*HWHI)
#define O_PLR     (O_CLR   + NB*CCH*HWLO)
#define O_MHH     (O_PLR   + NB*CCH*HWLO)
#define O_MLH     (O_MHH   + NB*9*HWHI)
#define O_MLL     (O_MLH   + NB*25*HWHI)
#define O_MHL     (O_MLL   + NB*25*HWLO)
#define O_MASKHR  (O_MHL   + NB*9*HWLO)
#define O_PART_HI (O_MASKHR + NB*9*HWHI)
#define O_PART_LO (O_PART_HI + NSPL*NB*25*HWHI)
#define SCRATCH_TOTAL (O_PART_LO + NSPL*NB*25*HWLO)

__device__ float g_scratch[SCRATCH_TOTAL];

template<int K>
__device__ __forceinline__ void wsoftmax(float* v, const float* hs) {
    float mx = v[0];
#pragma unroll
    for (int i = 1; i < K; i++) mx = fmaxf(mx, v[i]);
    float s = 0.f;
#pragma unroll
    for (int i = 0; i < K; i++) { v[i] = __expf(v[i] - mx) * hs[i]; s += v[i]; }
    float inv = 1.f / s;
#pragma unroll
    for (int i = 0; i < K; i++) v[i] *= inv;
}

template<int H, int W>
__device__ __forceinline__ float ldclamp(const float* __restrict__ base, int y, int x) {
    bool ok = ((unsigned)y < (unsigned)H) && ((unsigned)x < (unsigned)W);
    int ys = min(max(y, 0), H - 1);
    int xs = min(max(x, 0), W - 1);
    float v = base[(size_t)ys * W + xs];
    return ok ? v : 0.f;
}

__device__ __forceinline__ uint32_t smem_u32(const void* p) {
    uint32_t a;
    asm("{ .reg .u64 t; cvta.to.shared.u64 t, %1; cvt.u32.u64 %0, t; }" : "=r"(a) : "l"(p));
    return a;
}
__device__ __forceinline__ void cp16(uint32_t dst, const void* src) {
    asm volatile("cp.async.cg.shared.global [%0], [%1], 16;" :: "r"(dst), "l"(src));
}

// Precomputed halo-staging geometry (sync LDG version)
template<int H, int W, int TH, int TW, int NTHREADS>
struct StageGeom {
    static constexpr int HALO_C = TW + 2;
    static constexpr int HALO   = (TH + 2) * HALO_C;
    static constexpr int TWP    = TW + 4;
    static constexpr int NLD    = (HALO + NTHREADS - 1) / NTHREADS;
    int  offg[NLD];
    int  offd[NLD];
    bool ok[NLD];
    __device__ __forceinline__ void init(int t, int gy0, int gx0) {
#pragma unroll
        for (int j = 0; j < NLD; j++) {
            int e = j * NTHREADS + t;
            bool val = (e < HALO);
            int ec = val ? e : 0;
            int r = ec / HALO_C;
            int c = ec - r * HALO_C;
            int y = gy0 + r - 1, x = gx0 + c - 1;
            ok[j] = val && ((unsigned)y < (unsigned)H) && ((unsigned)x < (unsigned)W);
            int yc = min(max(y, 0), H - 1);
            int xc = min(max(x, 0), W - 1);
            offg[j] = yc * W + xc;
            offd[j] = val ? (r * TWP + c) : (TWP - 1);
        }
    }
    __device__ __forceinline__ void run(const float* __restrict__ xc, float* __restrict__ xd) const {
#pragma unroll
        for (int j = 0; j < NLD; j++) {
            float v = xc[offg[j]];
            xd[offd[j]] = ok[j] ? v : 0.f;
        }
    }
};

// ---------------- 1x1 conv = GEMM (scalar FFMA, cp.async double-buffered) ----------------
__global__ void __launch_bounds__(256)
gemm1x1_k(const float* __restrict__ X, const float* __restrict__ W,
          const float* __restrict__ bias, float* __restrict__ Y, int HW)
{
    __shared__ float Ws[2][16][32];
    __shared__ float Xs[2][16][128];
    int t   = threadIdx.x;
    int pxt = blockIdx.x, cot = blockIdx.y, nb = blockIdx.z;
    const float* Xb = X + (size_t)nb * CIN * HW + pxt * 128;
    const float* Wb = W + (size_t)cot * 32 * CIN;
    float acc[4][4];
#pragma unroll
    for (int i = 0; i < 4; i++)
#pragma unroll
        for (int j = 0; j < 4; j++) acc[i][j] = 0.f;

    int co_s = (t >> 5) * 4;
    int px_s = (t & 31) * 4;
    int xc = t >> 4;
    int xp = (t & 15) * 8;
    int wc = t >> 2;
    int wk = (t & 3) * 4;

    uint32_t xdst0 = smem_u32(&Xs[0][xc][xp]);
    uint32_t xdst1 = smem_u32(&Xs[1][xc][xp]);

    {
        const float* src = Xb + (size_t)xc * HW + xp;
        cp16(xdst0, src);
        cp16(xdst0 + 16, src + 4);
        asm volatile("cp.async.commit_group;");
        if (t < 128) {
            float4 w4 = *(const float4*)(Wb + (size_t)wc * CIN + wk);
            Ws[0][wk + 0][wc] = w4.x; Ws[0][wk + 1][wc] = w4.y;
            Ws[0][wk + 2][wc] = w4.z; Ws[0][wk + 3][wc] = w4.w;
        }
    }

    for (int c = 0; c < 16; c++) {
        int buf = c & 1;
        asm volatile("cp.async.wait_group 0;");
        __syncthreads();
        if (c < 15) {
            int kc = (c + 1) * 16;
            const float* src = Xb + (size_t)(kc + xc) * HW + xp;
            uint32_t xd = (buf ? xdst0 : xdst1);
            cp16(xd, src);
            cp16(xd + 16, src + 4);
            asm volatile("cp.async.commit_group;");
            if (t < 128) {
                float4 w4 = *(const float4*)(Wb + (size_t)wc * CIN + kc + wk);
                float (*Wn)[32] = Ws[buf ^ 1];
                Wn[wk + 0][wc] = w4.x; Wn[wk + 1][wc] = w4.y;
                Wn[wk + 2][wc] = w4.z; Wn[wk + 3][wc] = w4.w;
            }
        }
#pragma unroll
        for (int k = 0; k < 16; k++) {
            float4 a = *(const float4*)&Ws[buf][k][co_s];
            float4 b = *(const float4*)&Xs[buf][k][px_s];
            acc[0][0] = fmaf(a.x, b.x, acc[0][0]); acc[0][1] = fmaf(a.x, b.y, acc[0][1]);
            acc[0][2] = fmaf(a.x, b.z, acc[0][2]); acc[0][3] = fmaf(a.x, b.w, acc[0][3]);
            acc[1][0] = fmaf(a.y, b.x, acc[1][0]); acc[1][1] = fmaf(a.y, b.y, acc[1][1]);
            acc[1][2] = fmaf(a.y, b.z, acc[1][2]); acc[1][3] = fmaf(a.y, b.w, acc[1][3]);
            acc[2][0] = fmaf(a.z, b.x, acc[2][0]); acc[2][1] = fmaf(a.z, b.y, acc[2][1]);
            acc[2][2] = fmaf(a.z, b.z, acc[2][2]); acc[2][3] = fmaf(a.z, b.w, acc[2][3]);
            acc[3][0] = fmaf(a.w, b.x, acc[3][0]); acc[3][1] = fmaf(a.w, b.y, acc[3][1]);
            acc[3][2] = fmaf(a.w, b.z, acc[3][2]); acc[3][3] = fmaf(a.w, b.w, acc[3][3]);
        }
    }
    float* Yb = Y + (size_t)nb * CCH * HW + (size_t)(cot * 32) * HW + pxt * 128;
#pragma unroll
    for (int i = 0; i < 4; i++) {
        float bv = bias ? __ldg(&bias[cot * 32 + co_s + i]) : 0.f;
        float4 o = make_float4(acc[i][0] + bv, acc[i][1] + bv, acc[i][2] + bv, acc[i][3] + bv);
        *(float4*)(Yb + (size_t)(co_s + i) * HW + px_s) = o;
    }
}

// ---------------- 3x3 conv split-K partial, 2 px/thread (CO=25) ----------------
template<int CO, int TH, int TW, int CSPL, int H, int Wd>
__global__ void __launch_bounds__(128)
conv3x3_part_k(const float* __restrict__ X, const float* __restrict__ W,
               float* __restrict__ P)
{
    constexpr int CH = 8;
    constexpr int HW = H * Wd;
    __shared__ float xs[CH][TH + 2][TW + 4];
    __shared__ float ws[CH][CO][12];
    int t    = threadIdx.x;
    int row  = t / (TW / 2);
    int col2 = (t % (TW / 2)) * 2;
    int gx0 = blockIdx.x * TW;
    int gy0 = blockIdx.y * TH;
    int nb = blockIdx.z / NSPL;
    int sp = blockIdx.z % NSPL;
    int c0 = sp * CSPL;
    const float* Xb = X + (size_t)nb * CCH * HW;

    StageGeom<H, Wd, TH, TW, 128> sg;
    sg.init(t, gy0, gx0);

    float acc[CO][2];
#pragma unroll
    for (int i = 0; i < CO; i++) { acc[i][0] = 0.f; acc[i][1] = 0.f; }

    for (int cc = c0; cc < c0 + CSPL; cc += CH) {
#pragma unroll
        for (int ch = 0; ch < CH; ch++)
            sg.run(Xb + (size_t)(cc + ch) * HW, &xs[ch][0][0]);
        for (int p = t; p < CH * CO; p += 128) {
            int ch = p / CO, co = p - ch * CO;
            const float* wsrc = W + (size_t)co * CCH * 9 + (size_t)(cc + ch) * 9;
            float* wdst = &ws[ch][co][0];
#pragma unroll
            for (int k = 0; k < 9; k++) wdst[k] = wsrc[k];
        }
        __syncthreads();
#pragma unroll 2
        for (int ch = 0; ch < CH; ch++) {
            float xv[3][4];
#pragma unroll
            for (int r = 0; r < 3; r++) {
                float2 a0 = *(const float2*)&xs[ch][row + r][col2];
                float2 a1 = *(const float2*)&xs[ch][row + r][col2 + 2];
                xv[r][0] = a0.x; xv[r][1] = a0.y; xv[r][2] = a1.x; xv[r][3] = a1.y;
            }
#pragma unroll
            for (int co = 0; co < CO; co++) {
                float4 wa = *(const float4*)&ws[ch][co][0];
                float4 wb = *(const float4*)&ws[ch][co][4];
                float  w8 = ws[ch][co][8];
                float s0, s1;
                s0 = wa.x * xv[0][0];            s1 = wa.x * xv[0][1];
                s0 = fmaf(wa.y, xv[0][1], s0);   s1 = fmaf(wa.y, xv[0][2], s1);
                s0 = fmaf(wa.z, xv[0][2], s0);   s1 = fmaf(wa.z, xv[0][3], s1);
                s0 = fmaf(wa.w, xv[1][0], s0);   s1 = fmaf(wa.w, xv[1][1], s1);
                s0 = fmaf(wb.x, xv[1][1], s0);   s1 = fmaf(wb.x, xv[1][2], s1);
                s0 = fmaf(wb.y, xv[1][2], s0);   s1 = fmaf(wb.y, xv[1][3], s1);
                s0 = fmaf(wb.z, xv[2][0], s0);   s1 = fmaf(wb.z, xv[2][1], s1);
                s0 = fmaf(wb.w, xv[2][1], s0);   s1 = fmaf(wb.w, xv[2][2], s1);
                s0 = fmaf(w8 ,  xv[2][2], s0);   s1 = fmaf(w8 ,  xv[2][3], s1);
                acc[co][0] += s0; acc[co][1] += s1;
            }
        }
        __syncthreads();
    }
    float* Pb = P + ((size_t)sp * NB + nb) * CO * HW + (gy0 + row) * Wd + gx0 + col2;
#pragma unroll
    for (int co = 0; co < CO; co++)
        *(float2*)&Pb[(size_t)co * HW] = make_float2(acc[co][0], acc[co][1]);
}

// ---------------- 3x3 conv split-K partial, 4 px/thread (CO=9) ----------------
template<int CO, int TH, int TW, int CSPL, int H, int Wd>
__global__ void __launch_bounds__(128)
conv3x3_part4_k(const float* __restrict__ X, const float* __restrict__ W,
                float* __restrict__ P)
{
    constexpr int CH = 8;
    constexpr int HW = H * Wd;
    __shared__ float xs[CH][TH + 2][TW + 4];
    __shared__ float ws[CH][CO][12];
    int t    = threadIdx.x;
    int row  = t / (TW / 4);
    int col4 = (t % (TW / 4)) * 4;
    int gx0 = blockIdx.x * TW;
    int gy0 = blockIdx.y * TH;
    int nb = blockIdx.z / NSPL;
    int sp = blockIdx.z % NSPL;
    int c0 = sp * CSPL;
    const float* Xb = X + (size_t)nb * CCH * HW;

    StageGeom<H, Wd, TH, TW, 128> sg;
    sg.init(t, gy0, gx0);

    float acc[CO][4];
#pragma unroll
    for (int i = 0; i < CO; i++)
#pragma unroll
        for (int j = 0; j < 4; j++) acc[i][j] = 0.f;

    for (int cc = c0; cc < c0 + CSPL; cc += CH) {
#pragma unroll
        for (int ch = 0; ch < CH; ch++)
            sg.run(Xb + (size_t)(cc + ch) * HW, &xs[ch][0][0]);
        for (int p = t; p < CH * CO; p += 128) {
            int ch = p / CO, co = p - ch * CO;
            const float* wsrc = W + (size_t)co * CCH * 9 + (size_t)(cc + ch) * 9;
            float* wdst = &ws[ch][co][0];
#pragma unroll
            for (int k = 0; k < 9; k++) wdst[k] = wsrc[k];
        }
        __syncthreads();
#pragma unroll 2
        for (int ch = 0; ch < CH; ch++) {
            float xv[3][6];
#pragma unroll
            for (int r = 0; r < 3; r++) {
                float2 a0 = *(const float2*)&xs[ch][row + r][col4];
                float2 a1 = *(const float2*)&xs[ch][row + r][col4 + 2];
                float2 a2 = *(const float2*)&xs[ch][row + r][col4 + 4];
                xv[r][0] = a0.x; xv[r][1] = a0.y; xv[r][2] = a1.x;
                xv[r][3] = a1.y; xv[r][4] = a2.x; xv[r][5] = a2.y;
            }
#pragma unroll
            for (int co = 0; co < CO; co++) {
                float4 wa = *(const float4*)&ws[ch][co][0];
                float4 wb = *(const float4*)&ws[ch][co][4];
                float  w8 = ws[ch][co][8];
#pragma unroll
                for (int j = 0; j < 4; j++) {
                    float s = acc[co][j];
                    s = fmaf(wa.x, xv[0][j    ], s);
                    s = fmaf(wa.y, xv[0][j + 1], s);
                    s = fmaf(wa.z, xv[0][j + 2], s);
                    s = fmaf(wa.w, xv[1][j    ], s);
                    s = fmaf(wb.x, xv[1][j + 1], s);
                    s = fmaf(wb.y, xv[1][j + 2], s);
                    s = fmaf(wb.z, xv[2][j    ], s);
                    s = fmaf(wb.w, xv[2][j + 1], s);
                    s = fmaf(w8 ,  xv[2][j + 2], s);
                    acc[co][j] = s;
                }
            }
        }
        __syncthreads();
    }
    float* Pb = P + ((size_t)sp * NB + nb) * CO * HW + (gy0 + row) * Wd + gx0 + col4;
#pragma unroll
    for (int co = 0; co < CO; co++)
        *(float4*)&Pb[(size_t)co * HW] = make_float4(acc[co][0], acc[co][1], acc[co][2], acc[co][3]);
}

// ---------------- reduce NSPL partials + bias ----------------
__global__ void __launch_bounds__(256)
reduceN_bias_k(const float* __restrict__ P, const float* __restrict__ bias,
               float* __restrict__ Y, int CO, int HW, int perSplit)
{
    int i = (blockIdx.x * blockDim.x + threadIdx.x) * 4;
    if (i >= perSplit) return;
    float4 s = *(const float4*)&P[i];
#pragma unroll
    for (int k = 1; k < NSPL; k++) {
        float4 a = *(const float4*)&P[(size_t)k * perSplit + i];
        s.x += a.x; s.y += a.y; s.z += a.z; s.w += a.w;
    }
    int co = (i / HW) % CO;
    float bv = __ldg(&bias[co]);
    s.x += bv; s.y += bv; s.z += bv; s.w += bv;
    *(float4*)&Y[i] = s;
}

// ---------------- residual CARAFE k=3 up=1 (sync staging) ----------------
template<bool NORM, int CCHUNK>
__global__ void __launch_bounds__(128)
carafe3_k(const float* __restrict__ X, const float* __restrict__ M,
          const float* __restrict__ ham, float* __restrict__ Y, int C, int nCT)
{
    constexpr int CH = 8;
    __shared__ float xs[CH][6][68];
    int t = threadIdx.x;
    int row  = t >> 5;
    int col2 = (t & 31) * 2;
    int gx0 = blockIdx.x * 64;
    int gy0 = blockIdx.y * 4;
    int nb = blockIdx.z / nCT;
    int c0 = (blockIdx.z % nCT) * CCHUNK;
    int py = gy0 + row, px = gx0 + col2;

    StageGeom<HHI, WHI, 4, 64, 128> sg;
    sg.init(t, gy0, gx0);

    float w0[9], w1[9];
    {
        const float* Mb = M + (size_t)nb * 9 * HWHI + py * WHI + px;
#pragma unroll
        for (int k = 0; k < 9; k++) { w0[k] = Mb[(size_t)k * HWHI]; w1[k] = Mb[(size_t)k * HWHI + 1]; }
    }
    if (NORM) {
        float hv[9];
#pragma unroll
        for (int k = 0; k < 9; k++) hv[k] = __ldg(&ham[k]);
        wsoftmax<9>(w0, hv);
        wsoftmax<9>(w1, hv);
    }
    const float* Xb = X + (size_t)nb * C * HWHI;
    float*       Yb = Y + (size_t)nb * C * HWHI + (size_t)py * WHI + px;

    for (int cc = c0; cc < c0 + CCHUNK; cc += CH) {
#pragma unroll
        for (int ch = 0; ch < CH; ch++)
            sg.run(Xb + (size_t)(cc + ch) * HWHI, &xs[ch][0][0]);
        __syncthreads();
#pragma unroll
        for (int ch = 0; ch < CH; ch++) {
            float xv[3][4];
#pragma unroll
            for (int r = 0; r < 3; r++) {
                float2 a0 = *(const float2*)&xs[ch][row + r][col2];
                float2 a1 = *(const float2*)&xs[ch][row + r][col2 + 2];
                xv[r][0] = a0.x; xv[r][1] = a0.y; xv[r][2] = a1.x; xv[r][3] = a1.y;
            }
            float s0 = 0.f, s1 = 0.f;
#pragma unroll
            for (int p = 0; p < 3; p++)
#pragma unroll
                for (int q = 0; q < 3; q++) {
                    s0 = fmaf(w0[p * 3 + q], xv[p][q],     s0);
                    s1 = fmaf(w1[p * 3 + q], xv[p][q + 1], s1);
                }
            float2 o = make_float2(2.f * xv[1][1] - s0, 2.f * xv[1][2] - s1);
            *(float2*)&Yb[(size_t)(cc + ch) * HWHI] = o;
        }
        __syncthreads();
    }
}

// ---------------- mask_lr_n ----------------
__global__ void __launch_bounds__(256)
mask_fuse_lr_k(const float* __restrict__ mlh, const float* __restrict__ mll,
               const float* __restrict__ ham5, float* __restrict__ out)
{
    __shared__ float xs[25][12][12];
    __shared__ float hs[25];
    int t = threadIdx.x;
    int tx = t & 15, ty = t >> 4;
    int gx0 = blockIdx.x * 16, gy0 = blockIdx.y * 16, nb = blockIdx.z;
    int ly0 = gy0 / 2 - 2, lx0 = gx0 / 2 - 2;
    if (t < 25) hs[t] = ham5[t];
    if (ty < 12 && tx < 12) {
        int gy = ly0 + ty, gx = lx0 + tx;
#pragma unroll
        for (int ch = 0; ch < 25; ch++)
            xs[ch][ty][tx] = ldclamp<HLO, WLO>(mll + ((size_t)nb * 25 + ch) * HWLO, gy, gx);
    }
    __syncthreads();
    int py = gy0 + ty, px = gx0 + tx;
    float m[25];
    {
        const float* p = mlh + (size_t)nb * 25 * HWHI + py * WHI + px;
#pragma unroll
        for (int ch = 0; ch < 25; ch++) m[ch] = p[(size_t)ch * HWHI];
    }
    float wgt[25];
#pragma unroll
    for (int ch = 0; ch < 25; ch++) wgt[ch] = m[ch];
    wsoftmax<25>(wgt, hs);

    int rl = ty >> 1, cl = tx >> 1;
    float o[25];
#pragma unroll
    for (int ch = 0; ch < 25; ch++) {
        float s = 0.f;
#pragma unroll
        for (int p = 0; p < 5; p++)
#pragma unroll
            for (int q = 0; q < 5; q++)
                s = fmaf(wgt[p * 5 + q], xs[ch][rl + p][cl + q], s);
        o[ch] = m[ch] + s;
    }
    wsoftmax<25>(o, hs);
    float* op = out + (size_t)nb * 25 * HWHI + py * WHI + px;
#pragma unroll
    for (int ch = 0; ch < 25; ch++) op[(size_t)ch * HWHI] = o[ch];
}

// ---------------- mask_hr_n ----------------
__global__ void __launch_bounds__(256)
mask_fuse_hr_k(const float* __restrict__ mhh, const float* __restrict__ mhl,
               const float* __restrict__ maskn, const float* __restrict__ ham3,
               float* __restrict__ outm)
{
    __shared__ float xs[9][12][12];
    __shared__ float hs[9];
    int t = threadIdx.x;
    int tx = t & 15, ty = t >> 4;
    int gx0 = blockIdx.x * 16, gy0 = blockIdx.y * 16, nb = blockIdx.z;
    int ly0 = gy0 / 2 - 2, lx0 = gx0 / 2 - 2;
    if (t < 9) hs[t] = ham3[t];
    if (ty < 12 && tx < 12) {
        int gy = ly0 + ty, gx = lx0 + tx;
#pragma unroll
        for (int ch = 0; ch < 9; ch++)
            xs[ch][ty][tx] = ldclamp<HLO, WLO>(mhl + ((size_t)nb * 9 + ch) * HWLO, gy, gx);
    }
    __syncthreads();
    int py = gy0 + ty, px = gx0 + tx;
    float wgt[25];
    {
        const float* p = maskn + (size_t)nb * 25 * HWHI + py * WHI + px;
#pragma unroll
        for (int ch = 0; ch < 25; ch++) wgt[ch] = p[(size_t)ch * HWHI];
    }
    int rl = ty >> 1, cl = tx >> 1;
    float o[9];
    const float* mb = mhh + (size_t)nb * 9 * HWHI + py * WHI + px;
#pragma unroll
    for (int ch = 0; ch < 9; ch++) {
        float s = 0.f;
#pragma unroll
        for (int p = 0; p < 5; p++)
#pragma unroll
            for (int q = 0; q < 5; q++)
                s = fmaf(wgt[p * 5 + q], xs[ch][rl + p][cl + q], s);
        o[ch] = mb[(size_t)ch * HWHI] + s;
    }
    wsoftmax<9>(o, hs);
    float* op = outm + (size_t)nb * 9 * HWHI + py * WHI + px;
#pragma unroll
    for (int ch = 0; ch < 9; ch++) op[(size_t)ch * HWHI] = o[ch];
}

// ---------------- lr_out = carafe(P, mask_lr_n, 5, up2) + b_proj ----------------
__global__ void __launch_bounds__(256)
carafe_proj_k(const float* __restrict__ P, const float* __restrict__ maskn,
              const float* __restrict__ bproj, float* __restrict__ out)
{
    __shared__ float xs[8][12][12];
    int t = threadIdx.x;
    int tx = t & 15, ty = t >> 4;
    int gx0 = blockIdx.x * 16, gy0 = blockIdx.y * 16;
    int nb = blockIdx.z >> 2;
    int c0 = (blockIdx.z & 3) * 24;
    int ly0 = gy0 / 2 - 2, lx0 = gx0 / 2 - 2;
    int py = gy0 + ty, px = gx0 + tx;
    int rl = ty >> 1, cl = tx >> 1;

    float wgt[25];
    {
        const float* p = maskn + (size_t)nb * 25 * HWHI + py * WHI + px;
#pragma unroll
        for (int ch = 0; ch < 25; ch++) wgt[ch] = p[(size_t)ch * HWHI];
    }
    const float* Pb = P + (size_t)nb * CCH * HWLO;
    bool ld_ok = (ty < 12 && tx < 12);
    int gy = ly0 + ty, gx = lx0 + tx;

    for (int cc = c0; cc < c0 + 24; cc += 8) {
        if (ld_ok) {
#pragma unroll
            for (int ch = 0; ch < 8; ch++)
                xs[ch][ty][tx] = ldclamp<HLO, WLO>(Pb + (size_t)(cc + ch) * HWLO, gy, gx);
        }
        __syncthreads();
#pragma unroll
        for (int ch = 0; ch < 8; ch++) {
            float s = 0.f;
#pragma unroll
            for (int p = 0; p < 5; p++)
#pragma unroll
                for (int q = 0; q < 5; q++)
                    s = fmaf(wgt[p * 5 + q], xs[ch][rl + p][cl + q], s);
            out[((size_t)nb * CCH + cc + ch) * HWHI + py * WHI + px] = s + __ldg(&bproj[cc + ch]);
        }
        __syncthreads();
    }
}

// ---------------- launch ----------------
static cudaStream_t g_s1 = nullptr;
static cudaEvent_t  g_evA = nullptr, g_evB = nullptr, g_evC = nullptr, g_evD = nullptr;

extern "C" void kernel_launch(void* const* d_in, const int* in_sizes, int n_in,
                              void* d_out, int out_size)
{
    if (!g_s1) {
        cudaStreamCreateWithFlags(&g_s1, cudaStreamNonBlocking);
        cudaEventCreateWithFlags(&g_evA, cudaEventDisableTiming);
        cudaEventCreateWithFlags(&g_evB, cudaEventDisableTiming);
        cudaEventCreateWithFlags(&g_evC, cudaEventDisableTiming);
        cudaEventCreateWithFlags(&g_evD, cudaEventDisableTiming);
    }
    const float* hr     = (const float*)d_in[0];
    const float* lr     = (const float*)d_in[1];
    const float* W_hrc  = (const float*)d_in[2];
    const float* b_hrc  = (const float*)d_in[3];
    const float* W_lrc  = (const float*)d_in[4];
    const float* b_lrc  = (const float*)d_in[5];
    const float* W_enc  = (const float*)d_in[6];
    const float* b_enc  = (const float*)d_in[7];
    const float* W_enc2 = (const float*)d_in[8];
    const float* b_enc2 = (const float*)d_in[9];
    const float* W_proj = (const float*)d_in[10];
    const float* b_proj = (const float*)d_in[11];
    const float* ham5   = (const float*)d_in[12];
    const float* ham3   = (const float*)d_in[13];
    float* out = (float*)d_out;

    float* base = nullptr;
    cudaGetSymbolAddress((void**)&base, g_scratch);
    float* chr     = base + O_CHR;
    float* chr2    = base + O_CHR2;
    float* clr     = base + O_CLR;
    float* plr     = base + O_PLR;
    float* mhh     = base + O_MHH;
    float* mlh     = base + O_MLH;
    float* mll     = base + O_MLL;
    float* mhl     = base + O_MHL;
    float* maskhr  = base + O_MASKHR;
    float* part_hi = base + O_PART_HI;
    float* part_lo = base + O_PART_LO;

    float* out_mask = out;
    float* out_hr   = out + (size_t)NB * 25 * HWHI;
    float* out_lr   = out_hr + (size_t)NB * CIN * HWHI;

    cudaStream_t s0 = 0;

    // fork
    cudaEventRecord(g_evA, s0);
    cudaStreamWaitEvent(g_s1, g_evA, 0);

    // (1..4) s0 head
    gemm1x1_k<<<dim3(HWHI / 128, 3, NB), 256, 0, s0>>>(hr, W_hrc, b_hrc, chr, HWHI);                       // 1
    conv3x3_part4_k<9, 8, 64, 16, HHI, WHI><<<dim3(2, 16, NB * NSPL), 128, 0, s0>>>(chr, W_enc2, part_hi); // 2
    reduceN_bias_k<<<(NB * 9 * HWHI / 4 + 255) / 256, 256, 0, s0>>>(part_hi, b_enc2, mhh, 9, HWHI, NB * 9 * HWHI); // 3
    carafe3_k<true, 32><<<dim3(2, 32, NB * 3), 128, 0, s0>>>(chr, mhh, ham3, chr2, CCH, 3);                // 4
    // (5) s1 first kernel
    gemm1x1_k<<<dim3(HWLO / 128, 3, NB), 256, 0, g_s1>>>(lr, W_lrc, b_lrc, clr, HWLO);                     // 5
    // (6) conv25-hi profiled by ncu -s 5 -c 1
    conv3x3_part_k<25, 4, 64, 16, HHI, WHI><<<dim3(2, 32, NB * NSPL), 128, 0, s0>>>(chr2, W_enc, part_hi); // 6
    reduceN_bias_k<<<(NB * 25 * HWHI / 4 + 255) / 256, 256, 0, s0>>>(part_hi, b_enc, mlh, 25, HWHI, NB * 25 * HWHI);

    // rest of s1 low-res chain
    gemm1x1_k<<<dim3(HWLO / 128, 3, NB), 256, 0, g_s1>>>(lr, W_proj, nullptr, plr, HWLO);
    conv3x3_part_k<25, 8, 32, 16, HLO, WLO><<<dim3(2, 8, NB * NSPL), 128, 0, g_s1>>>(clr, W_enc, part_lo);
    reduceN_bias_k<<<(NB * 25 * HWLO / 4 + 255) / 256, 256, 0, g_s1>>>(part_lo, b_enc, mll, 25, HWLO, NB * 25 * HWLO);
    conv3x3_part4_k<9, 16, 32, 16, HLO, WLO><<<dim3(2, 4, NB * NSPL), 128, 0, g_s1>>>(clr, W_enc2, part_lo);
    reduceN_bias_k<<<(NB * 9 * HWLO / 4 + 255) / 256, 256, 0, g_s1>>>(part_lo, b_enc2, mhl, 9, HWLO, NB * 9 * HWLO);
    cudaEventRecord(g_evB, g_s1);

    // join lr chain, compute mask_lr_n
    cudaStreamWaitEvent(s0, g_evB, 0);
    mask_fuse_lr_k<<<dim3(8, 8, NB), 256, 0, s0>>>(mlh, mll, ham5, out_mask);

    // fork: carafe_proj only needs out_mask + plr
    cudaEventRecord(g_evC, s0);
    cudaStreamWaitEvent(g_s1, g_evC, 0);
    carafe_proj_k<<<dim3(8, 8, NB * 4), 256, 0, g_s1>>>(plr, out_mask, b_proj, out_lr);
    cudaEventRecord(g_evD, g_s1);

    // s0: mask_hr_n + hr residual (CCHUNK=8: occupancy for the big C=256 carafe)
    mask_fuse_hr_k<<<dim3(8, 8, NB), 256, 0, s0>>>(mhh, mhl, out_mask, ham3, maskhr);
    carafe3_k<false, 8><<<dim3(2, 32, NB * 32), 128, 0, s0>>>(hr, maskhr, ham3, out_hr, CIN, 32);

    // join
    cudaStreamWaitEvent(s0, g_evD, 0);
}